// round 2
// baseline (speedup 1.0000x reference)
#include <cuda_runtime.h>
#include <math.h>

// Problem constants (match reference_code)
#define BB   2
#define HH   112
#define WW   112
#define HW   (HH * WW)        // 12544
#define NPIX (BB * HW)        // 25088
#define EPSV 1e-7f
// Inclusion threshold for scatter: g >= 0.69  <=>  q <= eps - ln(0.69)
// (slightly below the 0.70 output threshold so boundary rounding matches ref)
#define QMAX 0.3710637f

#define NTHREAD 256
#define NBLOCK  (NPIX / NTHREAD)   // 98 blocks — all co-resident on 148 SMs

// Self-cleaning scratch: zero at module load; every launch ends by resetting
// it to zero, so each graph replay starts from a clean state.
__device__ int g_scratch[NPIX];

// Software grid barrier (valid because grid fits in one wave).
__device__ unsigned g_bar_count = 0;
__device__ volatile unsigned g_bar_gen = 0;

__global__ __launch_bounds__(NTHREAD)
void fused_gaussian_kernel(const float* __restrict__ variance,
                           const float* __restrict__ center,
                           float* __restrict__ out,
                           int out_size) {
    const int t = blockIdx.x * NTHREAD + threadIdx.x;   // 0..NPIX-1 exactly
    const int b = t / HW;
    const int p = t - b * HW;

    // ---------------- Phase 1: scatter ----------------
    {
        float cm = center[t];                 // [B,1,H,W] contiguous
        float m  = (cm > 0.7f) ? 1.0f : 0.0f;

        const float* vb = variance + (size_t)b * 3 * HW;
        float vx = vb[p] * m;
        float vy = vb[HW + p] * m;

        if (vx + vy != 0.0f) {                // matches torch.nonzero(vx+vy)
            float v2    = vb[2 * HW + p];
            float theta = 3.14f * (1.0f / (1.0f + expf(-v2)));
            float s  = sinf(theta);
            float co = cosf(theta);

            float var_x = vx * vx + EPSV;
            float var_y = vy * vy + EPSV;
            float a  = co * co / (2.0f * var_x) + s * s / (2.0f * var_y);
            float bq = -2.0f * s * co / (4.0f * var_x) + 2.0f * s * co / (4.0f * var_y);
            float c  = s * s / (2.0f * var_x) + co * co / (2.0f * var_y);

            int pr = p / WW;
            int pc = p - pr * WW;

            // q >= (di^2+dj^2)/(2*max(var)) => bounded support radius
            float maxvar = fmaxf(var_x, var_y);
            int R = (int)ceilf(sqrtf(2.0f * QMAX * maxvar)) + 1;
            if (R > 111) R = 111;

            int i0 = max(0, pr - R), i1 = min(HH - 1, pr + R);
            int j0 = max(0, pc - R), j1 = min(WW - 1, pc + R);

            int* outb = g_scratch + (size_t)b * HW;
            for (int i = i0; i <= i1; ++i) {
                float di  = (float)(i - pr);
                float adi = a * di * di;
                float bdi = 2.0f * bq * di;
                for (int j = j0; j <= j1; ++j) {
                    float dj = (float)(j - pc);
                    float q  = adi + bdi * dj + c * dj * dj;
                    if (q > QMAX) continue;        // g < 0.69: can never matter
                    float g = expf(-q + EPSV);
                    atomicMax(&outb[i * WW + j], __float_as_int(g));
                }
            }
        }
    }

    // ---------------- Grid barrier ----------------
    __threadfence();          // make this block's atomics globally visible
    __syncthreads();
    if (threadIdx.x == 0) {
        unsigned g = g_bar_gen;
        __threadfence();      // order the gen read before the arrival
        unsigned ticket = atomicAdd(&g_bar_count, 1u);
        if (ticket == NBLOCK - 1) {
            g_bar_count = 0;  // safe: all blocks have arrived
            __threadfence();
            g_bar_gen = g + 1;
        } else {
            while (g_bar_gen == g) { /* spin */ }
        }
    }
    __syncthreads();
    __threadfence();          // acquire: see all other blocks' scatter atomics

    // ---------------- Phase 2: threshold + write + reset scratch ----------------
    {
        float v = __int_as_float(g_scratch[t]);
        out[t] = (v >= 0.7f) ? v : 0.0f;
        g_scratch[t] = 0;     // clean for the next graph replay

        // Zero any tail of the output buffer (e.g. packed flag) — thread 0 only.
        if (t == 0) {
            for (int k = NPIX; k < out_size; ++k) out[k] = 0.0f;
        }
    }
}

extern "C" void kernel_launch(void* const* d_in, const int* in_sizes, int n_in,
                              void* d_out, int out_size) {
    // metadata order: x, variance, center_map, conv_w, conv_b
    const float* variance = (const float*)d_in[1];
    const float* center   = (const float*)d_in[2];
    float* out            = (float*)d_out;

    fused_gaussian_kernel<<<NBLOCK, NTHREAD>>>(variance, center, out, out_size);
}

// round 3
// speedup vs baseline: 1.0246x; 1.0246x over previous
#include <cuda_runtime.h>
#include <math.h>

// Problem constants (match reference_code)
#define BB   2
#define HH   112
#define WW   112
#define HW   (HH * WW)        // 12544
#define NPIX (BB * HW)        // 25088
#define EPSV 1e-7f
// Scatter inclusion bound: g >= 0.69  <=>  q <= EPSV - ln(0.69) ~= 0.3710637
// (slightly below the 0.70 output threshold; boundary handled exactly in phase 2)
#define QMAX 0.3710637f

#define NTHREAD 256
#define NBLOCK  (NPIX / NTHREAD)   // 98 blocks — all co-resident in one wave

// Self-cleaning scratch: zero at module load; phase 2 resets it each launch.
// Holds key = float_bits(QMAX - q_min) per pixel; 0 == no contribution.
__device__ int g_scratch[NPIX];

// Software grid barrier (grid fits in one wave).
__device__ unsigned g_bar_count = 0;
__device__ volatile unsigned g_bar_gen = 0;

__global__ __launch_bounds__(NTHREAD)
void fused_gaussian_kernel(const float* __restrict__ variance,
                           const float* __restrict__ center,
                           float* __restrict__ out,
                           int out_size) {
    const int t = blockIdx.x * NTHREAD + threadIdx.x;   // 0..NPIX-1 exactly
    const int b = t / HW;
    const int p = t - b * HW;

    // ---------------- Phase 1: scatter min-q as RED.MAX(QMAX - q) ----------------
    {
        float cm = center[t];                 // [B,1,H,W] contiguous
        float m  = (cm > 0.7f) ? 1.0f : 0.0f;

        const float* vb = variance + (size_t)b * 3 * HW;
        float vx = vb[p] * m;
        float vy = vb[HW + p] * m;

        if (vx + vy != 0.0f) {                // matches torch.nonzero(vx+vy)
            float v2    = vb[2 * HW + p];
            float theta = 3.14f * (1.0f / (1.0f + __expf(-v2)));
            float s, co;
            __sincosf(theta, &s, &co);

            float var_x = vx * vx + EPSV;
            float var_y = vy * vy + EPSV;
            float rx = 0.5f / var_x;          // 1/(2 var_x)
            float ry = 0.5f / var_y;          // 1/(2 var_y)
            float a  = co * co * rx + s * s * ry;
            float bq = s * co * (ry - rx);    // == -2sc/(4vx) + 2sc/(4vy)
            float c  = s * s * rx + co * co * ry;

            int pr = p / WW;
            int pc = p - pr * WW;

            // q >= (di^2+dj^2)/(2*max(var)) => bounded support radius
            float maxvar = fmaxf(var_x, var_y);
            int R = (int)ceilf(sqrtf(2.0f * QMAX * maxvar)) + 1;
            if (R > 111) R = 111;

            int i0 = max(0, pr - R), i1 = min(HH - 1, pr + R);
            int j0 = max(0, pc - R), j1 = min(WW - 1, pc + R);

            int* outb = g_scratch + (size_t)b * HW;
            for (int i = i0; i <= i1; ++i) {
                float di  = (float)(i - pr);
                float adi = a * di * di;
                float bdi = 2.0f * bq * di;
                int   row = i * WW;
                for (int j = j0; j <= j1; ++j) {
                    float dj = (float)(j - pc);
                    float q  = fmaf(c * dj, dj, fmaf(bdi, dj, adi));
                    if (q <= QMAX) {
                        // key in (0, QMAX]; larger key == smaller q == larger g
                        atomicMax(&outb[row + j], __float_as_int(QMAX - q));
                    }
                }
            }
        }
    }

    // ---------------- Grid barrier ----------------
    __threadfence();
    __syncthreads();
    if (threadIdx.x == 0) {
        unsigned g = g_bar_gen;
        __threadfence();
        unsigned ticket = atomicAdd(&g_bar_count, 1u);
        if (ticket == NBLOCK - 1) {
            g_bar_count = 0;
            __threadfence();
            g_bar_gen = g + 1;
        } else {
            while (g_bar_gen == g) { __nanosleep(64); }
        }
    }
    __syncthreads();
    __threadfence();

    // ---------------- Phase 2: exp + threshold + write + reset scratch ----------------
    {
        int   kbits = g_scratch[t];
        float v = 0.0f;
        if (kbits > 0) {
            float q = QMAX - __int_as_float(kbits);   // recovered q_min
            float g = expf(-q + EPSV);                // one precise exp per pixel
            v = (g >= 0.7f) ? g : 0.0f;
        }
        out[t] = v;
        g_scratch[t] = 0;     // clean for the next graph replay

        if (t == 0) {
            for (int k = NPIX; k < out_size; ++k) out[k] = 0.0f;
        }
    }
}

extern "C" void kernel_launch(void* const* d_in, const int* in_sizes, int n_in,
                              void* d_out, int out_size) {
    // metadata order: x, variance, center_map, conv_w, conv_b
    const float* variance = (const float*)d_in[1];
    const float* center   = (const float*)d_in[2];
    float* out            = (float*)d_out;

    fused_gaussian_kernel<<<NBLOCK, NTHREAD>>>(variance, center, out, out_size);
}

// round 4
// speedup vs baseline: 1.3540x; 1.3215x over previous
#include <cuda_runtime.h>
#include <math.h>

// Problem constants (match reference_code)
#define BB   2
#define HH   112
#define WW   112
#define HW   (HH * WW)        // 12544
#define NPIX (BB * HW)        // 25088
#define EPSV 1e-7f
// Scatter inclusion bound: g >= 0.69  <=>  q <= EPSV - ln(0.69) ~= 0.3710637
// (slightly below the 0.70 output threshold; exact >=0.7 test happens in kernel B)
#define QMAX 0.3710637f

#define NTHREAD 256
#define NBLOCK  (NPIX / NTHREAD)   // 98 blocks

// Self-cleaning scratch: zero at module load; kernel B resets it each launch,
// so every graph replay sees a clean buffer. Holds key = bits(QMAX - q_min);
// 0 == no contribution.
__device__ int g_scratch[NPIX];

// ---------------------------------------------------------------------------
// Kernel A: one thread per candidate center point; selected points RED.MAX
// their key into the bounded support window.
// ---------------------------------------------------------------------------
__global__ __launch_bounds__(NTHREAD)
void scatter_kernel(const float* __restrict__ variance,
                    const float* __restrict__ center) {
    const int t = blockIdx.x * NTHREAD + threadIdx.x;   // 0..NPIX-1 exactly
    const int b = t / HW;
    const int p = t - b * HW;

    float cm = center[t];                 // [B,1,H,W] contiguous
    float m  = (cm > 0.7f) ? 1.0f : 0.0f;

    const float* vb = variance + (size_t)b * 3 * HW;
    float vx = vb[p] * m;
    float vy = vb[HW + p] * m;
    if (vx + vy == 0.0f) return;          // matches torch.nonzero(vx+vy)

    float v2    = vb[2 * HW + p];
    float theta = 3.14f * (1.0f / (1.0f + __expf(-v2)));
    float s, co;
    __sincosf(theta, &s, &co);

    float var_x = vx * vx + EPSV;
    float var_y = vy * vy + EPSV;
    float rx = 0.5f / var_x;              // 1/(2 var_x)
    float ry = 0.5f / var_y;              // 1/(2 var_y)
    float a  = co * co * rx + s * s * ry;
    float bq = s * co * (ry - rx);        // == -2sc/(4vx) + 2sc/(4vy)
    float c  = s * s * rx + co * co * ry;

    int pr = p / WW;
    int pc = p - pr * WW;

    // q >= (di^2+dj^2)/(2*max(var)) => bounded support radius
    float maxvar = fmaxf(var_x, var_y);
    int R = (int)ceilf(sqrtf(2.0f * QMAX * maxvar)) + 1;
    if (R > 111) R = 111;

    int i0 = max(0, pr - R), i1 = min(HH - 1, pr + R);
    int j0 = max(0, pc - R), j1 = min(WW - 1, pc + R);

    int* outb = g_scratch + (size_t)b * HW;
    for (int i = i0; i <= i1; ++i) {
        float di  = (float)(i - pr);
        float adi = a * di * di;
        float bdi = 2.0f * bq * di;
        int   row = i * WW;
        #pragma unroll 4
        for (int j = j0; j <= j1; ++j) {
            float dj = (float)(j - pc);
            float q  = fmaf(c * dj, dj, fmaf(bdi, dj, adi));
            if (q <= QMAX) {
                // key in (0, QMAX]; larger key == smaller q == larger g
                atomicMax(&outb[row + j], __float_as_int(QMAX - q));
            }
        }
    }
}

// ---------------------------------------------------------------------------
// Kernel B: recover q_min, one exp per pixel, exact >=0.7 threshold, write
// output, and reset the scratch for the next replay.
// ---------------------------------------------------------------------------
__global__ __launch_bounds__(NTHREAD)
void finalize_kernel(float* __restrict__ out, int out_size) {
    const int t = blockIdx.x * NTHREAD + threadIdx.x;   // 0..NPIX-1 exactly

    int   kbits = g_scratch[t];
    float v = 0.0f;
    if (kbits > 0) {
        float q = QMAX - __int_as_float(kbits);   // recovered q_min
        float g = expf(-q + EPSV);                // one precise exp per pixel
        v = (g >= 0.7f) ? g : 0.0f;
    }
    out[t] = v;
    g_scratch[t] = 0;     // clean for the next graph replay

    if (t == 0) {
        for (int k = NPIX; k < out_size; ++k) out[k] = 0.0f;
    }
}

extern "C" void kernel_launch(void* const* d_in, const int* in_sizes, int n_in,
                              void* d_out, int out_size) {
    // metadata order: x, variance, center_map, conv_w, conv_b
    const float* variance = (const float*)d_in[1];
    const float* center   = (const float*)d_in[2];
    float* out            = (float*)d_out;

    scatter_kernel<<<NBLOCK, NTHREAD>>>(variance, center);
    finalize_kernel<<<NBLOCK, NTHREAD>>>(out, out_size);
}